// round 14
// baseline (speedup 1.0000x reference)
#include <cuda_runtime.h>
#include <cuda_bf16.h>

#define U   2048
#define BSZ 16
#define DK  32
#define TM  128
#define TN  128
#define NTILES (U / TM)   // 16
#define NCTILES (U / TN)  // 16
#define LOG2E 1.4426950408889634f
#define PITCH 80          // smem row pitch (bytes): 64B data + 16B pad -> LDSM conflict-free

// Scratch (static __device__ — no allocation allowed)
__device__ float g_rowsum[6][BSZ][U];
__device__ float g_colpart[3][BSZ][NTILES][U];
__device__ float g_Bi[BSZ][3][64];

// ---- helpers ---------------------------------------------------------------
__device__ __forceinline__ float ex2(float x) {
    float r; asm("ex2.approx.f32 %0, %1;" : "=f"(r) : "f"(x)); return r;
}
__device__ __forceinline__ unsigned smem_u32(const void* p) {
    unsigned a;
    asm("{ .reg .u64 t; cvta.to.shared.u64 t, %1; cvt.u32.u64 %0, t; }" : "=r"(a) : "l"(p));
    return a;
}
__device__ __forceinline__ unsigned bf2u(float a, float b) {
    __nv_bfloat162 t = __floats2bfloat162_rn(a, b);
    return *reinterpret_cast<unsigned*>(&t);
}

#define LDSM4(r, a) \
    asm volatile("ldmatrix.sync.aligned.m8n8.x4.shared.b16 {%0,%1,%2,%3}, [%4];" \
        : "=r"((r)[0]), "=r"((r)[1]), "=r"((r)[2]), "=r"((r)[3]) : "r"(a))

#define MMA16816(d, a, b0, b1) \
    asm volatile("mma.sync.aligned.m16n8k16.row.col.f32.bf16.bf16.f32 " \
        "{%0,%1,%2,%3}, {%4,%5,%6,%7}, {%8,%9}, {%0,%1,%2,%3};" \
        : "+f"((d)[0]), "+f"((d)[1]), "+f"((d)[2]), "+f"((d)[3]) \
        : "r"((a)[0]), "r"((a)[1]), "r"((a)[2]), "r"((a)[3]), "r"(b0), "r"(b1))

// ---------------------------------------------------------------------------
// Kernel 1: gram via mma.sync (bf16 hh+hl+lh fp32 emulation) with per-nc
// fused EX2 + dual (row/col) reduction epilogue (interleaves MUFU/FADD with
// HMMA; D live range 16 regs instead of 64).
// grid = (rowTile, batch, pair); CTA = 8 warps as 4(M)x2(N); warp tile 32x64.
// ---------------------------------------------------------------------------
__global__ __launch_bounds__(256, 2) void gram_kernel(const float* __restrict__ A,
                                                      const float* __restrict__ V,
                                                      const float* __restrict__ L)
{
    __shared__ __align__(16) unsigned char sXhi[TM * PITCH];
    __shared__ __align__(16) unsigned char sXlo[TM * PITCH];
    __shared__ __align__(16) unsigned char sYhi[TN * PITCH];
    __shared__ __align__(16) unsigned char sYlo[TN * PITCH];
    __shared__ float colred[4][128];
    __shared__ float rowred[2][128];

    const int tileR = blockIdx.x;
    const int b     = blockIdx.y;
    const int p     = blockIdx.z;

    const float *X, *Y;
    if (p == 0)      { X = A; Y = V; }
    else if (p == 1) { X = A; Y = L; }
    else             { X = V; Y = L; }
    X += (size_t)b * U * DK;
    Y += (size_t)b * U * DK;

    const int tid  = threadIdx.x;
    const int warp = tid >> 5;
    const int lane = tid & 31;
    const int wr   = warp >> 1;   // 0..3 : M position (rows wr*32..+31)
    const int wc   = warp & 1;    // 0..1 : N position (cols wc*64..+63)

    // ---- stage X once: bf16 hi/lo split, pre-scaled by log2(e) ----
    for (int it = 0; it < 4; it++) {
        int idx = tid + it * 256;           // 0..1023
        int r   = idx >> 3;
        int kq  = (idx & 7) * 4;
        float4 v = *(const float4*)&X[(size_t)(tileR * TM + r) * DK + kq];
        v.x *= LOG2E; v.y *= LOG2E; v.z *= LOG2E; v.w *= LOG2E;
        __nv_bfloat16 h0 = __float2bfloat16(v.x), h1 = __float2bfloat16(v.y);
        __nv_bfloat16 h2 = __float2bfloat16(v.z), h3 = __float2bfloat16(v.w);
        float l0 = v.x - __bfloat162float(h0), l1 = v.y - __bfloat162float(h1);
        float l2 = v.z - __bfloat162float(h2), l3 = v.w - __bfloat162float(h3);
        int off = r * PITCH + kq * 2;
        *(unsigned*)&sXhi[off]     = bf2u(__bfloat162float(h0), __bfloat162float(h1));
        *(unsigned*)&sXhi[off + 4] = bf2u(__bfloat162float(h2), __bfloat162float(h3));
        *(unsigned*)&sXlo[off]     = bf2u(l0, l1);
        *(unsigned*)&sXlo[off + 4] = bf2u(l2, l3);
    }
    __syncthreads();

    const unsigned xh_u = smem_u32(sXhi);
    const unsigned xl_u = smem_u32(sXlo);
    const unsigned yh_u = smem_u32(sYhi);
    const unsigned yl_u = smem_u32(sYlo);

    // ---- hoist A fragments (X invariant across N-tiles) ----
    unsigned Ah[2][2][4], Al[2][2][4];
#pragma unroll
    for (int mi = 0; mi < 2; mi++)
#pragma unroll
        for (int kh = 0; kh < 2; kh++) {
            unsigned row  = wr * 32 + mi * 16 + (lane & 15);
            unsigned byte = kh * 32 + ((lane & 16) ? 16u : 0u);
            LDSM4(Ah[mi][kh], xh_u + row * PITCH + byte);
            LDSM4(Al[mi][kh], xl_u + row * PITCH + byte);
        }

    float rp[4] = {0.f, 0.f, 0.f, 0.f};   // row-sum partials (mi,half)

    for (int nt = 0; nt < NCTILES; nt++) {
        __syncthreads();   // prev iter: B ldmatrix + colred read done
        // ---- stage Y tile (bf16 hi/lo, unscaled) ----
        for (int it = 0; it < 4; it++) {
            int idx = tid + it * 256;
            int r   = idx >> 3;
            int kq  = (idx & 7) * 4;
            float4 v = *(const float4*)&Y[(size_t)(nt * TN + r) * DK + kq];
            __nv_bfloat16 h0 = __float2bfloat16(v.x), h1 = __float2bfloat16(v.y);
            __nv_bfloat16 h2 = __float2bfloat16(v.z), h3 = __float2bfloat16(v.w);
            float l0 = v.x - __bfloat162float(h0), l1 = v.y - __bfloat162float(h1);
            float l2 = v.z - __bfloat162float(h2), l3 = v.w - __bfloat162float(h3);
            int off = r * PITCH + kq * 2;
            *(unsigned*)&sYhi[off]     = bf2u(__bfloat162float(h0), __bfloat162float(h1));
            *(unsigned*)&sYhi[off + 4] = bf2u(__bfloat162float(h2), __bfloat162float(h3));
            *(unsigned*)&sYlo[off]     = bf2u(l0, l1);
            *(unsigned*)&sYlo[off + 4] = bf2u(l2, l3);
        }
        __syncthreads();

        // ---- per n16 block: 24 MMAs then immediate epilogue ----
#pragma unroll
        for (int nc = 0; nc < 4; nc++) {
            float d[2][2][4];
#pragma unroll
            for (int mi = 0; mi < 2; mi++)
#pragma unroll
                for (int nn = 0; nn < 2; nn++)
#pragma unroll
                    for (int c = 0; c < 4; c++) d[mi][nn][c] = 0.f;

            unsigned mm   = (unsigned)lane >> 3;
            unsigned brow = wc * 64 + nc * 16 + ((mm & 2) ? 8u : 0u) + (lane & 7);
#pragma unroll
            for (int kh = 0; kh < 2; kh++) {
                unsigned byte = kh * 32 + (mm & 1) * 16;
                unsigned bh[4], bl[4];
                LDSM4(bh, yh_u + brow * PITCH + byte);
                LDSM4(bl, yl_u + brow * PITCH + byte);
#pragma unroll
                for (int mi = 0; mi < 2; mi++) {
                    MMA16816(d[mi][0], Ah[mi][kh], bh[0], bh[1]);
                    MMA16816(d[mi][1], Ah[mi][kh], bh[2], bh[3]);
                    MMA16816(d[mi][0], Ah[mi][kh], bl[0], bl[1]);
                    MMA16816(d[mi][1], Ah[mi][kh], bl[2], bl[3]);
                    MMA16816(d[mi][0], Al[mi][kh], bh[0], bh[1]);
                    MMA16816(d[mi][1], Al[mi][kh], bh[2], bh[3]);
                }
            }

            // fused epilogue for this n16 block (nn = 2*nc + nn2)
#pragma unroll
            for (int nn2 = 0; nn2 < 2; nn2++) {
                float c0 = 0.f, c1 = 0.f;
#pragma unroll
                for (int mi = 0; mi < 2; mi++) {
                    float e0 = ex2(d[mi][nn2][0]);
                    float e1 = ex2(d[mi][nn2][1]);
                    float e2 = ex2(d[mi][nn2][2]);
                    float e3 = ex2(d[mi][nn2][3]);
                    rp[mi * 2 + 0] += e0 + e1;     // row g
                    rp[mi * 2 + 1] += e2 + e3;     // row g + 8
                    c0 += e0 + e2;
                    c1 += e1 + e3;
                }
                c0 += __shfl_xor_sync(0xffffffffu, c0, 4);
                c0 += __shfl_xor_sync(0xffffffffu, c0, 8);
                c0 += __shfl_xor_sync(0xffffffffu, c0, 16);
                c1 += __shfl_xor_sync(0xffffffffu, c1, 4);
                c1 += __shfl_xor_sync(0xffffffffu, c1, 8);
                c1 += __shfl_xor_sync(0xffffffffu, c1, 16);
                if (lane < 4) {
                    int col = wc * 64 + (2 * nc + nn2) * 8 + lane * 2;
                    colred[wr][col]     = c0;
                    colred[wr][col + 1] = c1;
                }
            }
        }
        __syncthreads();
        if (tid < 128) {
            float s = (colred[0][tid] + colred[1][tid]) + (colred[2][tid] + colred[3][tid]);
            g_colpart[p][b][tileR][nt * TN + tid] = s;
        }
    }

    // ---- row sums: reduce over lane column-groups, then across wc ----
#pragma unroll
    for (int i = 0; i < 4; i++) {
        rp[i] += __shfl_xor_sync(0xffffffffu, rp[i], 1);
        rp[i] += __shfl_xor_sync(0xffffffffu, rp[i], 2);
    }
    if ((lane & 3) == 0) {
        int g = lane >> 2;
        rowred[wc][wr * 32 + 0  + g] = rp[0];
        rowred[wc][wr * 32 + 8  + g] = rp[1];
        rowred[wc][wr * 32 + 16 + g] = rp[2];
        rowred[wc][wr * 32 + 24 + g] = rp[3];
    }
    __syncthreads();
    if (tid < 128)
        g_rowsum[2 * p][b][tileR * TM + tid] = rowred[0][tid] + rowred[1][tid];
}

// ---------------------------------------------------------------------------
// Kernel 2: finalize Bi rows; column-sum partial reduction fused inline
// (removes the separate reduce kernel). One CTA per (batch, pair).
// ---------------------------------------------------------------------------
__global__ __launch_bounds__(256) void finalize_kernel(const float* __restrict__ A,
                                                       const float* __restrict__ V,
                                                       const float* __restrict__ L)
{
    const int b = blockIdx.x;
    const int p = blockIdx.y;
    const float *X, *Y;
    if (p == 0)      { X = A; Y = V; }
    else if (p == 1) { X = A; Y = L; }
    else             { X = V; Y = L; }
    X += (size_t)b * U * DK;
    Y += (size_t)b * U * DK;

    __shared__ float X0[32], Y0[32];
    __shared__ float sred[8][64];

    const int tid = threadIdx.x;
    if (tid < 32)      X0[tid]      = X[tid];
    else if (tid < 64) Y0[tid - 32] = Y[tid - 32];
    __syncthreads();

    float O1[32], O2[32];
#pragma unroll
    for (int d = 0; d < 32; d++) { O1[d] = 0.f; O2[d] = 0.f; }

    for (int jj = tid; jj < U; jj += 256) {
        float xj[32], yj[32];
#pragma unroll
        for (int qq = 0; qq < 8; qq++) {
            float4 v = *(const float4*)&Y[(size_t)jj * DK + qq * 4];
            yj[qq*4+0] = v.x; yj[qq*4+1] = v.y; yj[qq*4+2] = v.z; yj[qq*4+3] = v.w;
            float4 ww = *(const float4*)&X[(size_t)jj * DK + qq * 4];
            xj[qq*4+0] = ww.x; xj[qq*4+1] = ww.y; xj[qq*4+2] = ww.z; xj[qq*4+3] = ww.w;
        }
        // colsum_j: deterministic inline reduction of the 16 tile partials
        float csum = 0.f;
#pragma unroll
        for (int tI = 0; tI < NTILES; tI++) csum += g_colpart[p][b][tI][jj];

        float d1 = 0.f, d2 = 0.f;
#pragma unroll
        for (int k = 0; k < 32; k++) {
            d1 = fmaf(X0[k], yj[k], d1);
            d2 = fmaf(xj[k], Y0[k], d2);
        }
        float w1 = ex2(d1 * LOG2E) / csum;
        float w2 = ex2(d2 * LOG2E) / g_rowsum[2 * p][b][jj];
#pragma unroll
        for (int k = 0; k < 32; k++) {
            O1[k] = fmaf(w1, yj[k], O1[k]);
            O2[k] = fmaf(w2, xj[k], O2[k]);
        }
    }

#pragma unroll
    for (int k = 0; k < 32; k++) {
        for (int o = 16; o > 0; o >>= 1) {
            O1[k] += __shfl_down_sync(0xffffffffu, O1[k], o);
            O2[k] += __shfl_down_sync(0xffffffffu, O2[k], o);
        }
    }
    const int w    = tid >> 5;
    const int lane = tid & 31;
    if (lane == 0) {
#pragma unroll
        for (int k = 0; k < 32; k++) {
            sred[w][k]      = O1[k];
            sred[w][k + 32] = O2[k];
        }
    }
    __syncthreads();
    if (tid < 64) {
        float s = 0.f;
#pragma unroll
        for (int tI = 0; tI < 8; tI++) s += sred[tI][tid];
        float a = (tid < 32) ? X0[tid] : Y0[tid - 32];
        g_Bi[b][p][tid] = s * a;
    }
}

// ---------------------------------------------------------------------------
// Kernel 3: fused head + broadcast. Every CTA redundantly computes the tiny
// FC head (inputs L2-resident) then writes its own output slice.
// ---------------------------------------------------------------------------
__global__ __launch_bounds__(256) void bcast_head_kernel(const float* __restrict__ fc1w,
                                                         const float* __restrict__ fc1b,
                                                         const float* __restrict__ fc2w,
                                                         float4* __restrict__ out)
{
    __shared__ float Wt[64][64];      // fc1w transposed
    __shared__ float Ci[48];
    __shared__ float colsum[3];
    __shared__ float4 srow[16][16];   // per-batch 64-float row as float4[16]

    const int tid  = threadIdx.x;
    const int warp = tid >> 5;
    const int lane = tid & 31;

    for (int i = tid; i < 64 * 64; i += 256) {
        int o = i >> 6, m = i & 63;
        Wt[m][o] = fc1w[i];
    }
    __syncthreads();

    for (int pr = warp; pr < 48; pr += 8) {
        const int b = pr / 3, k = pr % 3;
        float r0 = g_Bi[b][k][lane];
        float r1 = g_Bi[b][k][lane + 32];
        float h0 = fc1b[lane];
        float h1 = fc1b[lane + 32];
#pragma unroll 8
        for (int m = 0; m < 32; m++) {
            float rm = __shfl_sync(0xffffffffu, r0, m);
            h0 = fmaf(rm, Wt[m][lane],      h0);
            h1 = fmaf(rm, Wt[m][lane + 32], h1);
        }
#pragma unroll 8
        for (int m = 0; m < 32; m++) {
            float rm = __shfl_sync(0xffffffffu, r1, m);
            h0 = fmaf(rm, Wt[m + 32][lane],      h0);
            h1 = fmaf(rm, Wt[m + 32][lane + 32], h1);
        }
        float ci = tanhf(h0) * fc2w[lane] + tanhf(h1) * fc2w[lane + 32];
#pragma unroll
        for (int o = 16; o > 0; o >>= 1) ci += __shfl_down_sync(0xffffffffu, ci, o);
        if (lane == 0) Ci[pr] = ci;
    }
    __syncthreads();
    if (tid < 3) {
        float s = 0.f;
        for (int b = 0; b < 16; b++) s += expf(Ci[b * 3 + tid]);
        colsum[tid] = s;
    }
    __syncthreads();
    if (tid < 64) {
        for (int b = 0; b < 16; b++) {
            float s = 0.f;
#pragma unroll
            for (int k = 0; k < 3; k++) {
                float alpha = expf(Ci[b * 3 + k]) / colsum[k];
                s += alpha * g_Bi[b][k][tid];
            }
            ((float*)srow)[b * 64 + tid] = s;
        }
    }
    __syncthreads();

    // write this CTA's 1024-float4 slice
    int base = blockIdx.x * 1024 + tid;
#pragma unroll
    for (int q = 0; q < 4; q++) {
        int i  = base + q * 256;       // global float4 index
        int d4 = i & 15;
        int b  = i >> 15;              // 2048*16 float4 per batch
        out[i] = srow[b][d4];
    }
}

// ---------------------------------------------------------------------------
extern "C" void kernel_launch(void* const* d_in, const int* in_sizes, int n_in,
                              void* d_out, int out_size)
{
    const float* A    = (const float*)d_in[0];
    const float* V    = (const float*)d_in[1];
    const float* L    = (const float*)d_in[2];
    const float* fc1w = (const float*)d_in[3];
    const float* fc1b = (const float*)d_in[4];
    const float* fc2w = (const float*)d_in[5];

    dim3 g1(NTILES, BSZ, 3);
    gram_kernel<<<g1, 256>>>(A, V, L);
    finalize_kernel<<<dim3(BSZ, 3), 256>>>(A, V, L);
    bcast_head_kernel<<<512, 256>>>(fc1w, fc1b, fc2w, (float4*)d_out);
}

// round 15
// speedup vs baseline: 1.1406x; 1.1406x over previous
#include <cuda_runtime.h>
#include <cuda_bf16.h>

#define U   2048
#define BSZ 16
#define DK  32
#define TM  128
#define TN  128
#define NTILES (U / TM)   // 16
#define NCTILES (U / TN)  // 16
#define LOG2E  1.4426950408889634f
#define SQRTL2E 1.2011224087864498f   // sqrt(log2(e)); applied to BOTH operands
#define PITCH 80          // smem row pitch (bytes): conflict-free LDSM

// ---- dynamic smem layout ---------------------------------------------------
#define OFF_XHI   0
#define OFF_XLO   (TM * PITCH)                 // 10240
#define OFF_Y     (2 * TM * PITCH)            // 20480; per buffer q: hi, then lo
#define YBUF(q)   (OFF_Y + (q) * (2 * TN * PITCH))
#define OFF_COLR  (OFF_Y + 2 * 2 * TN * PITCH)     // 61440: float[4][128]
#define OFF_ROWR  (OFF_COLR + 4 * 128 * 4)         // 63488: float[2][128]
#define SMEM_TOTAL (OFF_ROWR + 2 * 128 * 4)        // 64512

// Scratch (static __device__ — no allocation allowed)
__device__ float g_rowsum[6][BSZ][U];
__device__ float g_colpart[3][BSZ][NTILES][U];
__device__ float g_Bi[BSZ][3][64];
__device__ float g_row[BSZ][64];
__device__ __nv_bfloat16 g_hi[3][BSZ * U * DK];   // sqrt(log2e)-scaled bf16 hi
__device__ __nv_bfloat16 g_lo[3][BSZ * U * DK];   // residual lo

// ---- helpers ---------------------------------------------------------------
__device__ __forceinline__ float ex2(float x) {
    float r; asm("ex2.approx.f32 %0, %1;" : "=f"(r) : "f"(x)); return r;
}
__device__ __forceinline__ unsigned smem_u32(const void* p) {
    unsigned a;
    asm("{ .reg .u64 t; cvta.to.shared.u64 t, %1; cvt.u32.u64 %0, t; }" : "=r"(a) : "l"(p));
    return a;
}
__device__ __forceinline__ unsigned bf2u(float a, float b) {
    __nv_bfloat162 t = __floats2bfloat162_rn(a, b);
    return *reinterpret_cast<unsigned*>(&t);
}
__device__ __forceinline__ float fast_tanh(float x) {
    float t = ex2(2.f * LOG2E * x);
    return 1.f - __fdividef(2.f, t + 1.f);
}

#define CP16(dst, src) \
    asm volatile("cp.async.cg.shared.global [%0], [%1], 16;" :: "r"(dst), "l"(src))
#define CP_COMMIT() asm volatile("cp.async.commit_group;")
#define CP_WAIT(n)  asm volatile("cp.async.wait_group %0;" :: "n"(n))

#define LDSM4(r, a) \
    asm volatile("ldmatrix.sync.aligned.m8n8.x4.shared.b16 {%0,%1,%2,%3}, [%4];" \
        : "=r"((r)[0]), "=r"((r)[1]), "=r"((r)[2]), "=r"((r)[3]) : "r"(a))

#define MMA16816(d, a, b0, b1) \
    asm volatile("mma.sync.aligned.m16n8k16.row.col.f32.bf16.bf16.f32 " \
        "{%0,%1,%2,%3}, {%4,%5,%6,%7}, {%8,%9}, {%0,%1,%2,%3};" \
        : "+f"((d)[0]), "+f"((d)[1]), "+f"((d)[2]), "+f"((d)[3]) \
        : "r"((a)[0]), "r"((a)[1]), "r"((a)[2]), "r"((a)[3]), "r"(b0), "r"(b1))

// ---------------------------------------------------------------------------
// Kernel 0: one-time bf16 hi/lo split of A/V/L, scaled by sqrt(log2 e).
// ---------------------------------------------------------------------------
__global__ void split_kernel(const float* __restrict__ A,
                             const float* __restrict__ V,
                             const float* __restrict__ L)
{
    int idx = blockIdx.x * 256 + threadIdx.x;     // float4 index over 3 modalities
    int mod = idx >> 18;                          // 262144 float4 per modality
    int e4  = idx & 0x3FFFF;
    const float* src = (mod == 0) ? A : (mod == 1 ? V : L);
    float4 v = ((const float4*)src)[e4];
    v.x *= SQRTL2E; v.y *= SQRTL2E; v.z *= SQRTL2E; v.w *= SQRTL2E;
    __nv_bfloat16 h0 = __float2bfloat16(v.x), h1 = __float2bfloat16(v.y);
    __nv_bfloat16 h2 = __float2bfloat16(v.z), h3 = __float2bfloat16(v.w);
    unsigned* hi = (unsigned*)g_hi[mod];
    unsigned* lo = (unsigned*)g_lo[mod];
    hi[e4 * 2]     = bf2u(__bfloat162float(h0), __bfloat162float(h1));
    hi[e4 * 2 + 1] = bf2u(__bfloat162float(h2), __bfloat162float(h3));
    lo[e4 * 2]     = bf2u(v.x - __bfloat162float(h0), v.y - __bfloat162float(h1));
    lo[e4 * 2 + 1] = bf2u(v.z - __bfloat162float(h2), v.w - __bfloat162float(h3));
}

// ---------------------------------------------------------------------------
// Kernel 1: gram via mma.sync bf16 hh+hl+lh, staging from precomputed splits
// with cp.async double buffering. Fused EX2 + dual reduction epilogue.
// grid = (rowTile, batch, pair); CTA = 8 warps as 4(M)x2(N).
// ---------------------------------------------------------------------------
__global__ __launch_bounds__(256, 2) void gram_kernel()
{
    extern __shared__ __align__(16) unsigned char smem[];
    const unsigned sb = smem_u32(smem);

    const int tileR = blockIdx.x;
    const int b     = blockIdx.y;
    const int p     = blockIdx.z;

    const int xm = (p == 2) ? 1 : 0;             // X modality: A,A,V
    const int ym = (p == 0) ? 1 : 2;             // Y modality: V,L,L
    const __nv_bfloat16* xhi = g_hi[xm] + (size_t)b * U * DK;
    const __nv_bfloat16* xlo = g_lo[xm] + (size_t)b * U * DK;
    const __nv_bfloat16* yhi = g_hi[ym] + (size_t)b * U * DK;
    const __nv_bfloat16* ylo = g_lo[ym] + (size_t)b * U * DK;

    const int tid  = threadIdx.x;
    const int warp = tid >> 5;
    const int lane = tid & 31;
    const int wr   = warp >> 1;
    const int wc   = warp & 1;

    float* colred = (float*)(smem + OFF_COLR);   // [4][128]
    float* rowred = (float*)(smem + OFF_ROWR);   // [2][128]

    // ---- prologue: cp.async X tile + Y tile 0 (one group) ----
    {
        int cc = tid;                            // 0..255; chunk = 16B = 8 bf16
#pragma unroll
        for (int it = 0; it < 2; it++, cc += 256) {  // 512 chunks per plane
            int r = cc >> 2, c = cc & 3;
            CP16(sb + OFF_XHI + r * PITCH + c * 16,
                 &xhi[((size_t)(tileR * TM + r)) * DK + c * 8]);
            CP16(sb + OFF_XLO + r * PITCH + c * 16,
                 &xlo[((size_t)(tileR * TM + r)) * DK + c * 8]);
            CP16(sb + YBUF(0) + r * PITCH + c * 16,
                 &yhi[((size_t)r) * DK + c * 8]);
            CP16(sb + YBUF(0) + TN * PITCH + r * PITCH + c * 16,
                 &ylo[((size_t)r) * DK + c * 8]);
        }
    }
    CP_COMMIT();
    CP_WAIT(0);
    __syncthreads();

    // ---- hoist A fragments ----
    unsigned Ah[2][2][4], Al[2][2][4];
#pragma unroll
    for (int mi = 0; mi < 2; mi++)
#pragma unroll
        for (int kh = 0; kh < 2; kh++) {
            unsigned row  = wr * 32 + mi * 16 + (lane & 15);
            unsigned byte = kh * 32 + ((lane & 16) ? 16u : 0u);
            LDSM4(Ah[mi][kh], sb + OFF_XHI + row * PITCH + byte);
            LDSM4(Al[mi][kh], sb + OFF_XLO + row * PITCH + byte);
        }

    float rp[4] = {0.f, 0.f, 0.f, 0.f};

    for (int nt = 0; nt < NCTILES; nt++) {
        // issue next tile's staging into the buffer consumed in iter nt-1
        if (nt + 1 < NCTILES) {
            const unsigned yb = sb + YBUF((nt + 1) & 1);
            int cc = tid;
#pragma unroll
            for (int it = 0; it < 2; it++, cc += 256) {
                int r = cc >> 2, c = cc & 3;
                size_t srow = (size_t)((nt + 1) * TN + r) * DK + c * 8;
                CP16(yb + r * PITCH + c * 16, &yhi[srow]);
                CP16(yb + TN * PITCH + r * PITCH + c * 16, &ylo[srow]);
            }
            CP_COMMIT();
            CP_WAIT(1);
        } else {
            CP_WAIT(0);
        }
        __syncthreads();

        const unsigned yh_u = sb + YBUF(nt & 1);
        const unsigned yl_u = yh_u + TN * PITCH;

        // ---- per n16 block: 24 MMAs + fused epilogue ----
#pragma unroll
        for (int nc = 0; nc < 4; nc++) {
            float d[2][2][4];
#pragma unroll
            for (int mi = 0; mi < 2; mi++)
#pragma unroll
                for (int nn = 0; nn < 2; nn++)
#pragma unroll
                    for (int c = 0; c < 4; c++) d[mi][nn][c] = 0.f;

            unsigned mm   = (unsigned)lane >> 3;
            unsigned brow = wc * 64 + nc * 16 + ((mm & 2) ? 8u : 0u) + (lane & 7);
#pragma unroll
            for (int kh = 0; kh < 2; kh++) {
                unsigned byte = kh * 32 + (mm & 1) * 16;
                unsigned bh[4], bl[4];
                LDSM4(bh, yh_u + brow * PITCH + byte);
                LDSM4(bl, yl_u + brow * PITCH + byte);
#pragma unroll
                for (int mi = 0; mi < 2; mi++) {
                    MMA16816(d[mi][0], Ah[mi][kh], bh[0], bh[1]);
                    MMA16816(d[mi][1], Ah[mi][kh], bh[2], bh[3]);
                    MMA16816(d[mi][0], Ah[mi][kh], bl[0], bl[1]);
                    MMA16816(d[mi][1], Ah[mi][kh], bl[2], bl[3]);
                    MMA16816(d[mi][0], Al[mi][kh], bh[0], bh[1]);
                    MMA16816(d[mi][1], Al[mi][kh], bh[2], bh[3]);
                }
            }

#pragma unroll
            for (int nn2 = 0; nn2 < 2; nn2++) {
                float c0 = 0.f, c1 = 0.f;
#pragma unroll
                for (int mi = 0; mi < 2; mi++) {
                    float e0 = ex2(d[mi][nn2][0]);
                    float e1 = ex2(d[mi][nn2][1]);
                    float e2 = ex2(d[mi][nn2][2]);
                    float e3 = ex2(d[mi][nn2][3]);
                    rp[mi * 2 + 0] += e0 + e1;
                    rp[mi * 2 + 1] += e2 + e3;
                    c0 += e0 + e2;
                    c1 += e1 + e3;
                }
                c0 += __shfl_xor_sync(0xffffffffu, c0, 4);
                c0 += __shfl_xor_sync(0xffffffffu, c0, 8);
                c0 += __shfl_xor_sync(0xffffffffu, c0, 16);
                c1 += __shfl_xor_sync(0xffffffffu, c1, 4);
                c1 += __shfl_xor_sync(0xffffffffu, c1, 8);
                c1 += __shfl_xor_sync(0xffffffffu, c1, 16);
                if (lane < 4) {
                    int col = wc * 64 + (2 * nc + nn2) * 8 + lane * 2;
                    colred[wr * 128 + col]     = c0;
                    colred[wr * 128 + col + 1] = c1;
                }
            }
        }
        __syncthreads();
        if (tid < 128) {
            float s = (colred[tid] + colred[128 + tid]) + (colred[256 + tid] + colred[384 + tid]);
            g_colpart[p][b][tileR][nt * TN + tid] = s;
        }
    }

    // ---- row sums ----
#pragma unroll
    for (int i = 0; i < 4; i++) {
        rp[i] += __shfl_xor_sync(0xffffffffu, rp[i], 1);
        rp[i] += __shfl_xor_sync(0xffffffffu, rp[i], 2);
    }
    if ((lane & 3) == 0) {
        int g = lane >> 2;
        rowred[wc * 128 + wr * 32 + 0  + g] = rp[0];
        rowred[wc * 128 + wr * 32 + 8  + g] = rp[1];
        rowred[wc * 128 + wr * 32 + 16 + g] = rp[2];
        rowred[wc * 128 + wr * 32 + 24 + g] = rp[3];
    }
    __syncthreads();
    if (tid < 128)
        g_rowsum[2 * p][b][tileR * TM + tid] = rowred[tid] + rowred[128 + tid];
}

// ---------------------------------------------------------------------------
// Kernel 2: deterministic reduction of column-sum partials.
// ---------------------------------------------------------------------------
__global__ void reduce_colpart_kernel()
{
    int idx = blockIdx.x * 256 + threadIdx.x;
    if (idx >= 3 * BSZ * U) return;
    int jj  = idx & (U - 1);
    int rem = idx / U;
    int b   = rem & (BSZ - 1);
    int p   = rem / BSZ;
    float s = 0.f;
#pragma unroll
    for (int tI = 0; tI < NTILES; tI++) s += g_colpart[p][b][tI][jj];
    g_rowsum[2 * p + 1][b][jj] = s;
}

// ---------------------------------------------------------------------------
// Kernel 3: finalize Bi rows (fp32 numerators). One CTA per (batch, pair).
// ---------------------------------------------------------------------------
__global__ __launch_bounds__(256) void finalize_kernel(const float* __restrict__ A,
                                                       const float* __restrict__ V,
                                                       const float* __restrict__ L)
{
    const int b = blockIdx.x;
    const int p = blockIdx.y;
    const float *X, *Y;
    if (p == 0)      { X = A; Y = V; }
    else if (p == 1) { X = A; Y = L; }
    else             { X = V; Y = L; }
    X += (size_t)b * U * DK;
    Y += (size_t)b * U * DK;

    __shared__ float X0[32], Y0[32];
    __shared__ float sred[8][64];

    const int tid = threadIdx.x;
    if (tid < 32)      X0[tid]      = X[tid];
    else if (tid < 64) Y0[tid - 32] = Y[tid - 32];
    __syncthreads();

    float O1[32], O2[32];
#pragma unroll
    for (int d = 0; d < 32; d++) { O1[d] = 0.f; O2[d] = 0.f; }

    for (int jj = tid; jj < U; jj += 256) {
        float xj[32], yj[32];
#pragma unroll
        for (int qq = 0; qq < 8; qq++) {
            float4 v = *(const float4*)&Y[(size_t)jj * DK + qq * 4];
            yj[qq*4+0] = v.x; yj[qq*4+1] = v.y; yj[qq*4+2] = v.z; yj[qq*4+3] = v.w;
            float4 ww = *(const float4*)&X[(size_t)jj * DK + qq * 4];
            xj[qq*4+0] = ww.x; xj[qq*4+1] = ww.y; xj[qq*4+2] = ww.z; xj[qq*4+3] = ww.w;
        }
        float d1 = 0.f, d2 = 0.f;
#pragma unroll
        for (int k = 0; k < 32; k++) {
            d1 = fmaf(X0[k], yj[k], d1);
            d2 = fmaf(xj[k], Y0[k], d2);
        }
        float w1 = ex2(d1 * LOG2E) / g_rowsum[2 * p + 1][b][jj];
        float w2 = ex2(d2 * LOG2E) / g_rowsum[2 * p][b][jj];
#pragma unroll
        for (int k = 0; k < 32; k++) {
            O1[k] = fmaf(w1, yj[k], O1[k]);
            O2[k] = fmaf(w2, xj[k], O2[k]);
        }
    }

#pragma unroll
    for (int k = 0; k < 32; k++) {
        for (int o = 16; o > 0; o >>= 1) {
            O1[k] += __shfl_down_sync(0xffffffffu, O1[k], o);
            O2[k] += __shfl_down_sync(0xffffffffu, O2[k], o);
        }
    }
    const int w    = tid >> 5;
    const int lane = tid & 31;
    if (lane == 0) {
#pragma unroll
        for (int k = 0; k < 32; k++) {
            sred[w][k]      = O1[k];
            sred[w][k + 32] = O2[k];
        }
    }
    __syncthreads();
    if (tid < 64) {
        float s = 0.f;
#pragma unroll
        for (int tI = 0; tI < 8; tI++) s += sred[tI][tid];
        float a = (tid < 32) ? X0[tid] : Y0[tid - 32];
        g_Bi[b][p][tid] = s * a;
    }
}

// ---------------------------------------------------------------------------
// Kernel 4: FC head (fast tanh/exp), batch softmax, combine.
// ---------------------------------------------------------------------------
__global__ __launch_bounds__(1024) void head_kernel(const float* __restrict__ fc1w,
                                                    const float* __restrict__ fc1b,
                                                    const float* __restrict__ fc2w)
{
    __shared__ float Wt[64][64];
    __shared__ float Ci[48];
    __shared__ float colsum[3];
    const int tid  = threadIdx.x;
    const int warp = tid >> 5;
    const int lane = tid & 31;

    for (int i = tid; i < 64 * 64; i += 1024) {
        int o = i >> 6, m = i & 63;
        Wt[m][o] = fc1w[i];
    }
    __syncthreads();

    for (int pr = warp; pr < 48; pr += 32) {
        const int b = pr / 3, k = pr % 3;
        float r0 = g_Bi[b][k][lane];
        float r1 = g_Bi[b][k][lane + 32];
        float h0 = fc1b[lane];
        float h1 = fc1b[lane + 32];
#pragma unroll 8
        for (int m = 0; m < 32; m++) {
            float rm = __shfl_sync(0xffffffffu, r0, m);
            h0 = fmaf(rm, Wt[m][lane],      h0);
            h1 = fmaf(rm, Wt[m][lane + 32], h1);
        }
#pragma unroll 8
        for (int m = 0; m < 32; m++) {
            float rm = __shfl_sync(0xffffffffu, r1, m);
            h0 = fmaf(rm, Wt[m + 32][lane],      h0);
            h1 = fmaf(rm, Wt[m + 32][lane + 32], h1);
        }
        float ci = fast_tanh(h0) * fc2w[lane] + fast_tanh(h1) * fc2w[lane + 32];
#pragma unroll
        for (int o = 16; o > 0; o >>= 1) ci += __shfl_down_sync(0xffffffffu, ci, o);
        if (lane == 0) Ci[pr] = ci;
    }
    __syncthreads();
    if (tid < 3) {
        float s = 0.f;
        for (int b = 0; b < 16; b++) s += ex2(LOG2E * Ci[b * 3 + tid]);
        colsum[tid] = s;
    }
    __syncthreads();
    if (tid < 64) {
        for (int b = 0; b < 16; b++) {
            float s = 0.f;
#pragma unroll
            for (int k = 0; k < 3; k++) {
                float alpha = ex2(LOG2E * Ci[b * 3 + k]) / colsum[k];
                s += alpha * g_Bi[b][k][tid];
            }
            g_row[b][tid] = s;
        }
    }
}

// ---------------------------------------------------------------------------
// Kernel 5: broadcast per-batch row to [B, U, 64].
// ---------------------------------------------------------------------------
__global__ void bcast_kernel(float4* __restrict__ out)
{
    int i = blockIdx.x * 256 + threadIdx.x;
    if (i >= BSZ * U * 16) return;
    int d4  = i & 15;
    int u_b = i >> 4;
    int b   = u_b >> 11;
    out[i] = ((const float4*)g_row)[b * 16 + d4];
}

// ---------------------------------------------------------------------------
extern "C" void kernel_launch(void* const* d_in, const int* in_sizes, int n_in,
                              void* d_out, int out_size)
{
    const float* A    = (const float*)d_in[0];
    const float* V    = (const float*)d_in[1];
    const float* L    = (const float*)d_in[2];
    const float* fc1w = (const float*)d_in[3];
    const float* fc1b = (const float*)d_in[4];
    const float* fc2w = (const float*)d_in[5];

    cudaFuncSetAttribute(gram_kernel, cudaFuncAttributeMaxDynamicSharedMemorySize, SMEM_TOTAL);

    split_kernel<<<3072, 256>>>(A, V, L);
    dim3 g1(NTILES, BSZ, 3);
    gram_kernel<<<g1, 256, SMEM_TOTAL>>>();
    reduce_colpart_kernel<<<(3 * BSZ * U + 255) / 256, 256>>>();
    finalize_kernel<<<dim3(BSZ, 3), 256>>>(A, V, L);
    head_kernel<<<1, 1024>>>(fc1w, fc1b, fc2w);
    bcast_kernel<<<(BSZ * U * 16 + 255) / 256, 256>>>((float4*)d_out);
}

// round 16
// speedup vs baseline: 1.1605x; 1.0175x over previous
#include <cuda_runtime.h>
#include <cuda_bf16.h>

#define U   2048
#define BSZ 16
#define DK  32
#define TM  128
#define TN  128
#define NTILES (U / TM)   // 16
#define NCTILES (U / TN)  // 16
#define NSEG 4
#define SEGJ (U / NSEG)   // 512
#define LOG2E  1.4426950408889634f
#define SQRTL2E 1.2011224087864498f   // sqrt(log2(e)); applied to BOTH operands
#define PITCH 80          // smem row pitch (bytes): conflict-free LDSM

// ---- dynamic smem layout ---------------------------------------------------
#define OFF_XHI   0
#define OFF_XLO   (TM * PITCH)                 // 10240
#define OFF_Y     (2 * TM * PITCH)            // 20480; per buffer q: hi, then lo
#define YBUF(q)   (OFF_Y + (q) * (2 * TN * PITCH))
#define OFF_COLR  (OFF_Y + 2 * 2 * TN * PITCH)     // 61440: float[4][128]
#define OFF_ROWR  (OFF_COLR + 4 * 128 * 4)         // 63488: float[2][128]
#define SMEM_TOTAL (OFF_ROWR + 2 * 128 * 4)        // 64512

// Scratch (static __device__ — no allocation allowed)
__device__ float g_rowsum[6][BSZ][U];              // [2p] = row sums; [2p+1] unused now
__device__ float g_colpart[3][BSZ][NTILES][U];
__device__ float g_part[3][BSZ][NSEG][64];         // finalize partials
__device__ float g_Bi[BSZ][3][64];
__device__ float g_row[BSZ][64];
__device__ __nv_bfloat16 g_hi[3][BSZ * U * DK];    // sqrt(log2e)-scaled bf16 hi
__device__ __nv_bfloat16 g_lo[3][BSZ * U * DK];    // residual lo

// ---- helpers ---------------------------------------------------------------
__device__ __forceinline__ float ex2(float x) {
    float r; asm("ex2.approx.f32 %0, %1;" : "=f"(r) : "f"(x)); return r;
}
__device__ __forceinline__ unsigned smem_u32(const void* p) {
    unsigned a;
    asm("{ .reg .u64 t; cvta.to.shared.u64 t, %1; cvt.u32.u64 %0, t; }" : "=r"(a) : "l"(p));
    return a;
}
__device__ __forceinline__ unsigned bf2u(float a, float b) {
    __nv_bfloat162 t = __floats2bfloat162_rn(a, b);
    return *reinterpret_cast<unsigned*>(&t);
}
__device__ __forceinline__ float fast_tanh(float x) {
    float t = ex2(2.f * LOG2E * x);
    return 1.f - __fdividef(2.f, t + 1.f);
}

#define CP16(dst, src) \
    asm volatile("cp.async.cg.shared.global [%0], [%1], 16;" :: "r"(dst), "l"(src))
#define CP_COMMIT() asm volatile("cp.async.commit_group;")
#define CP_WAIT(n)  asm volatile("cp.async.wait_group %0;" :: "n"(n))

#define LDSM4(r, a) \
    asm volatile("ldmatrix.sync.aligned.m8n8.x4.shared.b16 {%0,%1,%2,%3}, [%4];" \
        : "=r"((r)[0]), "=r"((r)[1]), "=r"((r)[2]), "=r"((r)[3]) : "r"(a))

#define MMA16816(d, a, b0, b1) \
    asm volatile("mma.sync.aligned.m16n8k16.row.col.f32.bf16.bf16.f32 " \
        "{%0,%1,%2,%3}, {%4,%5,%6,%7}, {%8,%9}, {%0,%1,%2,%3};" \
        : "+f"((d)[0]), "+f"((d)[1]), "+f"((d)[2]), "+f"((d)[3]) \
        : "r"((a)[0]), "r"((a)[1]), "r"((a)[2]), "r"((a)[3]), "r"(b0), "r"(b1))

// ---------------------------------------------------------------------------
// Kernel 0: one-time bf16 hi/lo split of A/V/L, scaled by sqrt(log2 e).
// ---------------------------------------------------------------------------
__global__ void split_kernel(const float* __restrict__ A,
                             const float* __restrict__ V,
                             const float* __restrict__ L)
{
    int idx = blockIdx.x * 256 + threadIdx.x;     // float4 index over 3 modalities
    int mod = idx >> 18;                          // 262144 float4 per modality
    int e4  = idx & 0x3FFFF;
    const float* src = (mod == 0) ? A : (mod == 1 ? V : L);
    float4 v = ((const float4*)src)[e4];
    v.x *= SQRTL2E; v.y *= SQRTL2E; v.z *= SQRTL2E; v.w *= SQRTL2E;
    __nv_bfloat16 h0 = __float2bfloat16(v.x), h1 = __float2bfloat16(v.y);
    __nv_bfloat16 h2 = __float2bfloat16(v.z), h3 = __float2bfloat16(v.w);
    unsigned* hi = (unsigned*)g_hi[mod];
    unsigned* lo = (unsigned*)g_lo[mod];
    hi[e4 * 2]     = bf2u(__bfloat162float(h0), __bfloat162float(h1));
    hi[e4 * 2 + 1] = bf2u(__bfloat162float(h2), __bfloat162float(h3));
    lo[e4 * 2]     = bf2u(v.x - __bfloat162float(h0), v.y - __bfloat162float(h1));
    lo[e4 * 2 + 1] = bf2u(v.z - __bfloat162float(h2), v.w - __bfloat162float(h3));
}

// ---------------------------------------------------------------------------
// Kernel 1: gram via mma.sync bf16 hh+hl+lh, staging from precomputed splits
// with cp.async double buffering. Fused EX2 + dual reduction epilogue.
// (unchanged from round 15 — profiled improvement kept)
// ---------------------------------------------------------------------------
__global__ __launch_bounds__(256, 2) void gram_kernel()
{
    extern __shared__ __align__(16) unsigned char smem[];
    const unsigned sb = smem_u32(smem);

    const int tileR = blockIdx.x;
    const int b     = blockIdx.y;
    const int p     = blockIdx.z;

    const int xm = (p == 2) ? 1 : 0;             // X modality: A,A,V
    const int ym = (p == 0) ? 1 : 2;             // Y modality: V,L,L
    const __nv_bfloat16* xhi = g_hi[xm] + (size_t)b * U * DK;
    const __nv_bfloat16* xlo = g_lo[xm] + (size_t)b * U * DK;
    const __nv_bfloat16* yhi = g_hi[ym] + (size_t)b * U * DK;
    const __nv_bfloat16* ylo = g_lo[ym] + (size_t)b * U * DK;

    const int tid  = threadIdx.x;
    const int warp = tid >> 5;
    const int lane = tid & 31;
    const int wr   = warp >> 1;
    const int wc   = warp & 1;

    float* colred = (float*)(smem + OFF_COLR);   // [4][128]
    float* rowred = (float*)(smem + OFF_ROWR);   // [2][128]

    // ---- prologue: cp.async X tile + Y tile 0 ----
    {
        int cc = tid;
#pragma unroll
        for (int it = 0; it < 2; it++, cc += 256) {
            int r = cc >> 2, c = cc & 3;
            CP16(sb + OFF_XHI + r * PITCH + c * 16,
                 &xhi[((size_t)(tileR * TM + r)) * DK + c * 8]);
            CP16(sb + OFF_XLO + r * PITCH + c * 16,
                 &xlo[((size_t)(tileR * TM + r)) * DK + c * 8]);
            CP16(sb + YBUF(0) + r * PITCH + c * 16,
                 &yhi[((size_t)r) * DK + c * 8]);
            CP16(sb + YBUF(0) + TN * PITCH + r * PITCH + c * 16,
                 &ylo[((size_t)r) * DK + c * 8]);
        }
    }
    CP_COMMIT();
    CP_WAIT(0);
    __syncthreads();

    // ---- hoist A fragments ----
    unsigned Ah[2][2][4], Al[2][2][4];
#pragma unroll
    for (int mi = 0; mi < 2; mi++)
#pragma unroll
        for (int kh = 0; kh < 2; kh++) {
            unsigned row  = wr * 32 + mi * 16 + (lane & 15);
            unsigned byte = kh * 32 + ((lane & 16) ? 16u : 0u);
            LDSM4(Ah[mi][kh], sb + OFF_XHI + row * PITCH + byte);
            LDSM4(Al[mi][kh], sb + OFF_XLO + row * PITCH + byte);
        }

    float rp[4] = {0.f, 0.f, 0.f, 0.f};

    for (int nt = 0; nt < NCTILES; nt++) {
        if (nt + 1 < NCTILES) {
            const unsigned yb = sb + YBUF((nt + 1) & 1);
            int cc = tid;
#pragma unroll
            for (int it = 0; it < 2; it++, cc += 256) {
                int r = cc >> 2, c = cc & 3;
                size_t srow = (size_t)((nt + 1) * TN + r) * DK + c * 8;
                CP16(yb + r * PITCH + c * 16, &yhi[srow]);
                CP16(yb + TN * PITCH + r * PITCH + c * 16, &ylo[srow]);
            }
            CP_COMMIT();
            CP_WAIT(1);
        } else {
            CP_WAIT(0);
        }
        __syncthreads();

        const unsigned yh_u = sb + YBUF(nt & 1);
        const unsigned yl_u = yh_u + TN * PITCH;

#pragma unroll
        for (int nc = 0; nc < 4; nc++) {
            float d[2][2][4];
#pragma unroll
            for (int mi = 0; mi < 2; mi++)
#pragma unroll
                for (int nn = 0; nn < 2; nn++)
#pragma unroll
                    for (int c = 0; c < 4; c++) d[mi][nn][c] = 0.f;

            unsigned mm   = (unsigned)lane >> 3;
            unsigned brow = wc * 64 + nc * 16 + ((mm & 2) ? 8u : 0u) + (lane & 7);
#pragma unroll
            for (int kh = 0; kh < 2; kh++) {
                unsigned byte = kh * 32 + (mm & 1) * 16;
                unsigned bh[4], bl[4];
                LDSM4(bh, yh_u + brow * PITCH + byte);
                LDSM4(bl, yl_u + brow * PITCH + byte);
#pragma unroll
                for (int mi = 0; mi < 2; mi++) {
                    MMA16816(d[mi][0], Ah[mi][kh], bh[0], bh[1]);
                    MMA16816(d[mi][1], Ah[mi][kh], bh[2], bh[3]);
                    MMA16816(d[mi][0], Ah[mi][kh], bl[0], bl[1]);
                    MMA16816(d[mi][1], Ah[mi][kh], bl[2], bl[3]);
                    MMA16816(d[mi][0], Al[mi][kh], bh[0], bh[1]);
                    MMA16816(d[mi][1], Al[mi][kh], bh[2], bh[3]);
                }
            }

#pragma unroll
            for (int nn2 = 0; nn2 < 2; nn2++) {
                float c0 = 0.f, c1 = 0.f;
#pragma unroll
                for (int mi = 0; mi < 2; mi++) {
                    float e0 = ex2(d[mi][nn2][0]);
                    float e1 = ex2(d[mi][nn2][1]);
                    float e2 = ex2(d[mi][nn2][2]);
                    float e3 = ex2(d[mi][nn2][3]);
                    rp[mi * 2 + 0] += e0 + e1;
                    rp[mi * 2 + 1] += e2 + e3;
                    c0 += e0 + e2;
                    c1 += e1 + e3;
                }
                c0 += __shfl_xor_sync(0xffffffffu, c0, 4);
                c0 += __shfl_xor_sync(0xffffffffu, c0, 8);
                c0 += __shfl_xor_sync(0xffffffffu, c0, 16);
                c1 += __shfl_xor_sync(0xffffffffu, c1, 4);
                c1 += __shfl_xor_sync(0xffffffffu, c1, 8);
                c1 += __shfl_xor_sync(0xffffffffu, c1, 16);
                if (lane < 4) {
                    int col = wc * 64 + (2 * nc + nn2) * 8 + lane * 2;
                    colred[wr * 128 + col]     = c0;
                    colred[wr * 128 + col + 1] = c1;
                }
            }
        }
        __syncthreads();
        if (tid < 128) {
            float s = (colred[tid] + colred[128 + tid]) + (colred[256 + tid] + colred[384 + tid]);
            g_colpart[p][b][tileR][nt * TN + tid] = s;
        }
    }

    // ---- row sums ----
#pragma unroll
    for (int i = 0; i < 4; i++) {
        rp[i] += __shfl_xor_sync(0xffffffffu, rp[i], 1);
        rp[i] += __shfl_xor_sync(0xffffffffu, rp[i], 2);
    }
    if ((lane & 3) == 0) {
        int g = lane >> 2;
        rowred[wc * 128 + wr * 32 + 0  + g] = rp[0];
        rowred[wc * 128 + wr * 32 + 8  + g] = rp[1];
        rowred[wc * 128 + wr * 32 + 16 + g] = rp[2];
        rowred[wc * 128 + wr * 32 + 24 + g] = rp[3];
    }
    __syncthreads();
    if (tid < 128)
        g_rowsum[2 * p][b][tileR * TM + tid] = rowred[tid] + rowred[128 + tid];
}

// ---------------------------------------------------------------------------
// Kernel 2: finalize partials. grid (BSZ, 3, NSEG) = 192 CTAs; each covers
// 512 j's with inline colsum reduction (replaces the separate reduce kernel
// AND the 48-CTA latency-bound finalize: 215-reg threads now do 2 j-iters).
// ---------------------------------------------------------------------------
__global__ __launch_bounds__(256) void finalize_partial_kernel(const float* __restrict__ A,
                                                               const float* __restrict__ V,
                                                               const float* __restrict__ L)
{
    const int b   = blockIdx.x;
    const int p   = blockIdx.y;
    const int seg = blockIdx.z;
    const float *X, *Y;
    if (p == 0)      { X = A; Y = V; }
    else if (p == 1) { X = A; Y = L; }
    else             { X = V; Y = L; }
    X += (size_t)b * U * DK;
    Y += (size_t)b * U * DK;

    __shared__ float X0[32], Y0[32];
    __shared__ float sred[8][64];

    const int tid = threadIdx.x;
    if (tid < 32)      X0[tid]      = X[tid];
    else if (tid < 64) Y0[tid - 32] = Y[tid - 32];
    __syncthreads();

    float O1[32], O2[32];
#pragma unroll
    for (int d = 0; d < 32; d++) { O1[d] = 0.f; O2[d] = 0.f; }

    for (int jj = seg * SEGJ + tid; jj < (seg + 1) * SEGJ; jj += 256) {
        float xj[32], yj[32];
#pragma unroll
        for (int qq = 0; qq < 8; qq++) {
            float4 v = *(const float4*)&Y[(size_t)jj * DK + qq * 4];
            yj[qq*4+0] = v.x; yj[qq*4+1] = v.y; yj[qq*4+2] = v.z; yj[qq*4+3] = v.w;
            float4 ww = *(const float4*)&X[(size_t)jj * DK + qq * 4];
            xj[qq*4+0] = ww.x; xj[qq*4+1] = ww.y; xj[qq*4+2] = ww.z; xj[qq*4+3] = ww.w;
        }
        // colsum_j: deterministic inline reduction of the 16 tile partials
        float csum = 0.f;
#pragma unroll
        for (int tI = 0; tI < NTILES; tI++) csum += g_colpart[p][b][tI][jj];

        float d1 = 0.f, d2 = 0.f;
#pragma unroll
        for (int k = 0; k < 32; k++) {
            d1 = fmaf(X0[k], yj[k], d1);
            d2 = fmaf(xj[k], Y0[k], d2);
        }
        float w1 = ex2(d1 * LOG2E) / csum;
        float w2 = ex2(d2 * LOG2E) / g_rowsum[2 * p][b][jj];
#pragma unroll
        for (int k = 0; k < 32; k++) {
            O1[k] = fmaf(w1, yj[k], O1[k]);
            O2[k] = fmaf(w2, xj[k], O2[k]);
        }
    }

#pragma unroll
    for (int k = 0; k < 32; k++) {
        for (int o = 16; o > 0; o >>= 1) {
            O1[k] += __shfl_down_sync(0xffffffffu, O1[k], o);
            O2[k] += __shfl_down_sync(0xffffffffu, O2[k], o);
        }
    }
    const int w    = tid >> 5;
    const int lane = tid & 31;
    if (lane == 0) {
#pragma unroll
        for (int k = 0; k < 32; k++) {
            sred[w][k]      = O1[k];
            sred[w][k + 32] = O2[k];
        }
    }
    __syncthreads();
    if (tid < 64) {
        float s = 0.f;
#pragma unroll
        for (int tI = 0; tI < 8; tI++) s += sred[tI][tid];
        g_part[p][b][seg][tid] = s;     // factor applied in head prologue
    }
}

// ---------------------------------------------------------------------------
// Kernel 3: head. Prologue combines the 4 finalize partials into g_Bi
// (scaled by f1_0 / f2_0), then FC + batch softmax + combine.
// ---------------------------------------------------------------------------
__global__ __launch_bounds__(1024) void head_kernel(const float* __restrict__ A,
                                                    const float* __restrict__ V,
                                                    const float* __restrict__ L,
                                                    const float* __restrict__ fc1w,
                                                    const float* __restrict__ fc1b,
                                                    const float* __restrict__ fc2w)
{
    __shared__ float Wt[64][64];
    __shared__ float Ci[48];
    __shared__ float colsum[3];
    const int tid  = threadIdx.x;
    const int warp = tid >> 5;
    const int lane = tid & 31;

    // combine partials -> g_Bi (3072 elements)
    for (int i = tid; i < 48 * 64; i += 1024) {
        int d  = i & 63;
        int bp = i >> 6;
        int p  = bp % 3;
        int b  = bp / 3;
        float s = (g_part[p][b][0][d] + g_part[p][b][1][d])
                + (g_part[p][b][2][d] + g_part[p][b][3][d]);
        const float *X, *Y;
        if (p == 0)      { X = A; Y = V; }
        else if (p == 1) { X = A; Y = L; }
        else             { X = V; Y = L; }
        float a = (d < 32) ? X[(size_t)b * U * DK + d]
                           : Y[(size_t)b * U * DK + (d - 32)];
        g_Bi[b][p][d] = s * a;
    }
    for (int i = tid; i < 64 * 64; i += 1024) {
        int o = i >> 6, m = i & 63;
        Wt[m][o] = fc1w[i];
    }
    __syncthreads();   // orders g_Bi global writes within this CTA

    for (int pr = warp; pr < 48; pr += 32) {
        const int b = pr / 3, k = pr % 3;
        float r0 = g_Bi[b][k][lane];
        float r1 = g_Bi[b][k][lane + 32];
        float h0 = fc1b[lane];
        float h1 = fc1b[lane + 32];
#pragma unroll 8
        for (int m = 0; m < 32; m++) {
            float rm = __shfl_sync(0xffffffffu, r0, m);
            h0 = fmaf(rm, Wt[m][lane],      h0);
            h1 = fmaf(rm, Wt[m][lane + 32], h1);
        }
#pragma unroll 8
        for (int m = 0; m < 32; m++) {
            float rm = __shfl_sync(0xffffffffu, r1, m);
            h0 = fmaf(rm, Wt[m + 32][lane],      h0);
            h1 = fmaf(rm, Wt[m + 32][lane + 32], h1);
        }
        float ci = fast_tanh(h0) * fc2w[lane] + fast_tanh(h1) * fc2w[lane + 32];
#pragma unroll
        for (int o = 16; o > 0; o >>= 1) ci += __shfl_down_sync(0xffffffffu, ci, o);
        if (lane == 0) Ci[pr] = ci;
    }
    __syncthreads();
    if (tid < 3) {
        float s = 0.f;
        for (int b = 0; b < 16; b++) s += ex2(LOG2E * Ci[b * 3 + tid]);
        colsum[tid] = s;
    }
    __syncthreads();
    if (tid < 64) {
        for (int b = 0; b < 16; b++) {
            float s = 0.f;
#pragma unroll
            for (int k = 0; k < 3; k++) {
                float alpha = ex2(LOG2E * Ci[b * 3 + k]) / colsum[k];
                s += alpha * g_Bi[b][k][tid];
            }
            g_row[b][tid] = s;
        }
    }
}

// ---------------------------------------------------------------------------
// Kernel 4: broadcast per-batch row to [B, U, 64].
// ---------------------------------------------------------------------------
__global__ void bcast_kernel(float4* __restrict__ out)
{
    int i = blockIdx.x * 256 + threadIdx.x;
    if (i >= BSZ * U * 16) return;
    int d4  = i & 15;
    int u_b = i >> 4;
    int b   = u_b >> 11;
    out[i] = ((const float4*)g_row)[b * 16 + d4];
}

// ---------------------------------------------------------------------------
extern "C" void kernel_launch(void* const* d_in, const int* in_sizes, int n_in,
                              void* d_out, int out_size)
{
    const float* A    = (const float*)d_in[0];
    const float* V    = (const float*)d_in[1];
    const float* L    = (const float*)d_in[2];
    const float* fc1w = (const float*)d_in[3];
    const float* fc1b = (const float*)d_in[4];
    const float* fc2w = (const float*)d_in[5];

    cudaFuncSetAttribute(gram_kernel, cudaFuncAttributeMaxDynamicSharedMemorySize, SMEM_TOTAL);

    split_kernel<<<3072, 256>>>(A, V, L);
    dim3 g1(NTILES, BSZ, 3);
    gram_kernel<<<g1, 256, SMEM_TOTAL>>>();
    finalize_partial_kernel<<<dim3(BSZ, 3, NSEG), 256>>>(A, V, L);
    head_kernel<<<1, 1024>>>(A, V, L, fc1w, fc1b, fc2w);
    bcast_kernel<<<(BSZ * U * 16 + 255) / 256, 256>>>((float4*)d_out);
}